// round 4
// baseline (speedup 1.0000x reference)
#include <cuda_runtime.h>
#include <cuda_bf16.h>
#include <math_constants.h>

// ============================================================================
// HVIN fully fused into ONE kernel:
//   prologue : stage weights, precompose (W_r o W_h) -> WC / W5 per block
//   body     : one block per image; maxpool -> coarse front -> coarse VI ->
//              upsample -> fine front -> fine VI -> final q + BN partials
//   epilogue : last block (atomic ticket) finalizes BN + dueling heads
// VI inner loops use packed fp32x2 FMA (FFMA2) with pair-duplicated weights.
// ============================================================================

#define N_IMG 128
#define KVI   16

typedef unsigned long long ull;

// ---------------- device scratch (no allocations allowed) -------------------
__device__ float g_partial[N_IMG * 20]; // per image: [c] sum, [10+c] sumsq
__device__ float g_qout[N_IMG * 10];    // q gathered at (S1, S2)
__device__ unsigned int g_tick;         // epilogue ticket (reset each launch)

// ---------------- packed fp32x2 helpers -------------------------------------
__device__ __forceinline__ ull pk2(float lo, float hi) {
    ull r; asm("mov.b64 %0, {%1,%2};" : "=l"(r) : "f"(lo), "f"(hi)); return r;
}
__device__ __forceinline__ void upk2(ull v, float& lo, float& hi) {
    asm("mov.b64 {%0,%1}, %2;" : "=f"(lo), "=f"(hi) : "l"(v));
}
__device__ __forceinline__ void fma2(ull& d, ull a, ull b) {
    asm("fma.rn.f32x2 %0, %1, %2, %3;" : "=l"(d) : "l"(a), "l"(b), "l"(d));
}

// ---------------- shared memory layout (float offsets) ----------------------
#define SM_WQF2 0        // 8640  conv_q_ws pair-duplicated (16,10,3,3,3)x2
#define SM_WQC2 8640     // 5760  vi_conv_q_ws pair-duplicated (16,10,2,3,3)x2
#define SM_WCF  14400    // 162   fine  WC[j(9)][ci(2)][i(9)]
#define SM_WCC  14562    // 162   coarse
#define SM_W5F  14724    // 50    fine  W5[ci][5x5]
#define SM_W5C  14774    // 50    coarse
#define SM_X    14824    // 9248  X pad-2 (also wh/wr staging scratch first)
#define SM_X1   24072    // 2592  pooled X pad-2
#define SM_R1   26664    // 1156  coarse r1, pad-1
#define SM_VA   27820    // 1156  coarse v A, pad-1
#define SM_VB   28976    // 1156  coarse v B
#define SM_SC   30132    // 1024  coarse s (32x32)
#define SM_RF   31156    // 8712  fine [m, r], pad-1
#define SM_VFA  39868    // 4356  fine v A, pad-1
#define SM_VFB  44224    // 4356  fine v B
#define SM_SF   48580    // 4096  fine s (64x64)
#define SM_RED  52676    // 320   BN block-reduce scratch
#define SM_TOT  52996
#define SMEM_BYTES (SM_TOT * 4)

// ============================================================================
// Fused r front-end: r = conv_r(conv_h(X)), SAME padding both stages.
// Interior: exact composed 5x5 (W5) on zero-padded X. Border: WC form with
// the clipped-h inside test (bit-exact vs reference).
// ============================================================================
template <int H, int ROW, int CHS>
__device__ __forceinline__ float rfront(const float* __restrict__ sxb,
                                        const float* __restrict__ w5,
                                        const float* __restrict__ wc,
                                        int y, int x) {
    float acc = 0.f;
    if (y >= 1 && y <= H - 2 && x >= 1 && x <= H - 2) {
#pragma unroll
        for (int ci = 0; ci < 2; ci++) {
            const float* xb = &sxb[ci * CHS + y * ROW + x];
#pragma unroll
            for (int fy = 0; fy < 5; fy++)
#pragma unroll
                for (int fx = 0; fx < 5; fx++)
                    acc = fmaf(w5[ci * 25 + fy * 5 + fx], xb[fy * ROW + fx], acc);
        }
    } else {
#pragma unroll
        for (int jy = 0; jy < 3; jy++)
#pragma unroll
            for (int jx = 0; jx < 3; jx++) {
                int py = y + jy - 1, px = x + jx - 1;
                if (py >= 0 && py < H && px >= 0 && px < H) {
                    const float* wcj = &wc[(jy * 3 + jx) * 18];
#pragma unroll
                    for (int ci = 0; ci < 2; ci++) {
                        const float* xb = &sxb[ci * CHS + (py + 1) * ROW + (px + 1)];
#pragma unroll
                        for (int iy = 0; iy < 3; iy++)
#pragma unroll
                            for (int ix = 0; ix < 3; ix++)
                                acc = fmaf(wcj[ci * 9 + iy * 3 + ix], xb[iy * ROW + ix], acc);
                    }
                }
            }
    }
    return acc;
}

// ============================================================================
__global__ __launch_bounds__(512) void k_main(
    const float* __restrict__ X, const int* __restrict__ S1, const int* __restrict__ S2,
    const float* __restrict__ wqf, const float* __restrict__ wqc,
    const float* __restrict__ whf, const float* __restrict__ wrf,
    const float* __restrict__ whc, const float* __restrict__ wrc,
    const float* __restrict__ gamma, const float* __restrict__ beta,
    const float* __restrict__ dw1, const float* __restrict__ dw2,
    float* __restrict__ out) {
    extern __shared__ float sm[];
    const int t = threadIdx.x;
    const int n = blockIdx.x;

    // ---- stage q-weights pair-duplicated (broadcast-ready LDS.64) --------
    for (int i = t; i < 4320; i += 512) {
        float w = wqf[i];
        sm[SM_WQF2 + 2 * i] = w; sm[SM_WQF2 + 2 * i + 1] = w;
    }
    for (int i = t; i < 2880; i += 512) {
        float w = wqc[i];
        sm[SM_WQC2 + 2 * i] = w; sm[SM_WQC2 + 2 * i + 1] = w;
    }
    // ---- stage raw h/r weights into X scratch ----------------------------
    for (int i = t; i < 2700; i += 512) sm[SM_X + i] = whf[i];
    for (int i = t; i < 1350; i += 512) sm[SM_X + 2700 + i] = wrf[i];
    for (int i = t; i < 2700; i += 512) sm[SM_X + 4050 + i] = whc[i];
    for (int i = t; i < 1350; i += 512) sm[SM_X + 6750 + i] = wrc[i];
    __syncthreads();

    // ---- compose WC[lvl] = sum_o wr[o][j] * wh[o][ci][i] -----------------
    if (t < 324) {
        int lvl = t / 162, rem = t % 162;
        int j = rem / 18, ci = (rem % 18) / 9, i = rem % 9;
        const float* wr = &sm[SM_X + (lvl ? 6750 : 2700)];
        const float* wh = &sm[SM_X + (lvl ? 4050 : 0)];
        float acc = 0.f;
        for (int o = 0; o < 150; o++)
            acc = fmaf(wr[o * 9 + j], wh[(o * 2 + ci) * 9 + i], acc);
        sm[(lvl ? SM_WCC : SM_WCF) + rem] = acc;
    }
    __syncthreads();

    // ---- W5 from WC, plus zero all work buffers --------------------------
    if (t < 100) {
        int lvl = t / 50, rem = t % 50;
        int ci = rem / 25, f = rem % 25, fy = f / 5, fx = f % 5;
        const float* wc = &sm[lvl ? SM_WCC : SM_WCF];
        float acc = 0.f;
        for (int jy = 0; jy < 3; jy++)
            for (int jx = 0; jx < 3; jx++) {
                int iy = fy - jy, ix = fx - jx;
                if (iy >= 0 && iy <= 2 && ix >= 0 && ix <= 2)
                    acc += wc[(jy * 3 + jx) * 18 + ci * 9 + iy * 3 + ix];
            }
        sm[(lvl ? SM_W5C : SM_W5F) + rem] = acc;
    }
    __syncthreads();   // W5 reads WC; zero of SM_X must wait for compose
    for (int i = SM_X + t; i < SM_RED; i += 512) sm[i] = 0.f;
    __syncthreads();

    // ---- load X into pad-2 smem ------------------------------------------
    for (int i = t; i < 8192; i += 512) {
        int ci = i >> 12, y = (i >> 6) & 63, x = i & 63;
        sm[SM_X + ci * 4624 + (y + 2) * 68 + (x + 2)] = X[n * 8192 + i];
    }
    __syncthreads();

    // ---- maxpool 2x2 -> X1 (pad-2) ---------------------------------------
    for (int i = t; i < 2048; i += 512) {
        int ci = i >> 10, y = (i >> 5) & 31, x = i & 31;
        const float* b = &sm[SM_X + ci * 4624 + (2 * y + 2) * 68 + (2 * x + 2)];
        float v = fmaxf(fmaxf(b[0], b[1]), fmaxf(b[68], b[69]));
        sm[SM_X1 + ci * 1296 + (y + 2) * 36 + (x + 2)] = v;
    }
    __syncthreads();

    // ---- coarse r1 -------------------------------------------------------
    for (int i = t; i < 1024; i += 512) {
        int y = i >> 5, x = i & 31;
        sm[SM_R1 + (y + 1) * 34 + (x + 1)] =
            rfront<32, 36, 1296>(&sm[SM_X1], &sm[SM_W5C], &sm[SM_WCC], y, x);
    }
    __syncthreads();

    // ---- coarse VI loop: 512 threads x 2 px, packed fp32x2 ---------------
    {
        float* vcc = sm + SM_VA;
        float* vcn = sm + SM_VB;
        const int cy = t >> 4, cx0 = (t & 15) * 2;
#pragma unroll 1
        for (int k = 0; k < KVI; k++) {
            ull pp[2][3][3];
#pragma unroll
            for (int r = 0; r < 3; r++) {
                const float* br = &sm[SM_R1 + (cy + r) * 34 + cx0];
                float c0 = br[0], c1 = br[1], c2 = br[2], c3 = br[3];
                pp[0][r][0] = pk2(c0, c1); pp[0][r][1] = pk2(c1, c2); pp[0][r][2] = pk2(c2, c3);
                const float* bv = &vcc[(cy + r) * 34 + cx0];
                float d0 = bv[0], d1 = bv[1], d2 = bv[2], d3 = bv[3];
                pp[1][r][0] = pk2(d0, d1); pp[1][r][1] = pk2(d1, d2); pp[1][r][2] = pk2(d2, d3);
            }
            float v0 = -CUDART_INF_F, v1 = v0;
            const ull* wp = reinterpret_cast<const ull*>(&sm[SM_WQC2]) + k * 180;
#pragma unroll 2
            for (int c = 0; c < 10; c++) {
                ull a = 0ull;
#pragma unroll
                for (int cin = 0; cin < 2; cin++)
#pragma unroll
                    for (int r = 0; r < 3; r++)
#pragma unroll
                        for (int s = 0; s < 3; s++)
                            fma2(a, wp[c * 18 + cin * 9 + r * 3 + s], pp[cin][r][s]);
                float f0, f1; upk2(a, f0, f1);
                v0 = fmaxf(v0, f0); v1 = fmaxf(v1, f1);
            }
            vcn[(cy + 1) * 34 + cx0 + 1] = v0;
            vcn[(cy + 1) * 34 + cx0 + 2] = v1;
            sm[SM_SC + cy * 32 + cx0 + 0] += v0;
            sm[SM_SC + cy * 32 + cx0 + 1] += v1;
            __syncthreads();
            float* tmp = vcc; vcc = vcn; vcn = tmp;
        }
    }

    // ---- upsample s/4 (jax linear half-pixel, edge-renorm == clamp) ------
    for (int i = t; i < 4096; i += 512) {
        int oy = i >> 6, ox = i & 63;
        int ty = oy >> 1, tx = ox >> 1;
        int ya, yb, xa, xb;
        float wya, wyb, wxa, wxb;
        if ((oy & 1) == 0) { ya = (ty > 0) ? ty - 1 : 0; yb = ty; wya = 0.25f; wyb = 0.75f; }
        else               { ya = ty; yb = (ty < 31) ? ty + 1 : 31; wya = 0.75f; wyb = 0.25f; }
        if ((ox & 1) == 0) { xa = (tx > 0) ? tx - 1 : 0; xb = tx; wxa = 0.25f; wxb = 0.75f; }
        else               { xa = tx; xb = (tx < 31) ? tx + 1 : 31; wxa = 0.75f; wxb = 0.25f; }
        float v = wya * (wxa * sm[SM_SC + ya * 32 + xa] + wxb * sm[SM_SC + ya * 32 + xb]) +
                  wyb * (wxa * sm[SM_SC + yb * 32 + xa] + wxb * sm[SM_SC + yb * 32 + xb]);
        sm[SM_RF + (oy + 1) * 66 + (ox + 1)] = v * 0.25f;
    }
    for (int i = t; i < 4096; i += 512) {
        int y = i >> 6, x = i & 63;
        sm[SM_RF + 4356 + (y + 1) * 66 + (x + 1)] =
            rfront<64, 68, 4624>(&sm[SM_X], &sm[SM_W5F], &sm[SM_WCF], y, x);
    }
    __syncthreads();

    // ---- fine VI loop: 512 threads x (4 px x 2 reps), packed fp32x2 ------
    float* vfc = sm + SM_VFA;
    float* vfn = sm + SM_VFB;
#pragma unroll 1
    for (int k = 0; k < KVI; k++) {
        const ull* wpk = reinterpret_cast<const ull*>(&sm[SM_WQF2]) + k * 270;
#pragma unroll 1
        for (int rep = 0; rep < 2; rep++) {
            int gid = t + rep * 512;
            int y = gid >> 4, x0 = (gid & 15) * 4;
            ull pp[3][3][5];
#pragma unroll
            for (int r = 0; r < 3; r++) {
                const float* b0 = &sm[SM_RF + (y + r) * 66 + x0];
                const float* b1 = b0 + 4356;
                const float* b2 = &vfc[(y + r) * 66 + x0];
#pragma unroll
                for (int p = 0; p < 5; p++) {
                    pp[0][r][p] = pk2(b0[p], b0[p + 1]);
                    pp[1][r][p] = pk2(b1[p], b1[p + 1]);
                    pp[2][r][p] = pk2(b2[p], b2[p + 1]);
                }
            }
            float v0 = -CUDART_INF_F, v1 = v0, v2 = v0, v3 = v0;
#pragma unroll 2
            for (int c = 0; c < 10; c++) {
                ull a01 = 0ull, a23 = 0ull;
                const ull* w = wpk + c * 27;
#pragma unroll
                for (int cin = 0; cin < 3; cin++)
#pragma unroll
                    for (int r = 0; r < 3; r++)
#pragma unroll
                        for (int s = 0; s < 3; s++) {
                            ull wv = w[cin * 9 + r * 3 + s];
                            fma2(a01, wv, pp[cin][r][s]);
                            fma2(a23, wv, pp[cin][r][s + 2]);
                        }
                float f0, f1, f2, f3;
                upk2(a01, f0, f1); upk2(a23, f2, f3);
                v0 = fmaxf(v0, f0); v1 = fmaxf(v1, f1);
                v2 = fmaxf(v2, f2); v3 = fmaxf(v3, f3);
            }
            vfn[(y + 1) * 66 + x0 + 1] = v0;
            vfn[(y + 1) * 66 + x0 + 2] = v1;
            vfn[(y + 1) * 66 + x0 + 3] = v2;
            vfn[(y + 1) * 66 + x0 + 4] = v3;
            sm[SM_SF + y * 64 + x0 + 0] += v0;
            sm[SM_SF + y * 64 + x0 + 1] += v1;
            sm[SM_SF + y * 64 + x0 + 2] += v2;
            sm[SM_SF + y * 64 + x0 + 3] += v3;
        }
        __syncthreads();
        float* tmp = vfc; vfc = vfn; vfn = tmp;
    }

    // ---- vbar = s/16 into current v buffer (ring still zero) -------------
    for (int i = t; i < 4096; i += 512) {
        int y = i >> 6, x = i & 63;
        vfc[(y + 1) * 66 + (x + 1)] = sm[SM_SF + i] * (1.f / 16.f);
    }
    __syncthreads();

    // ---- final q = conv([m, r, vbar], wqf[15]); BN partials; gather ------
    float psum[10], psq[10];
#pragma unroll
    for (int c = 0; c < 10; c++) { psum[c] = 0.f; psq[c] = 0.f; }
    const int s1 = S1[n], s2 = S2[n];
#pragma unroll 1
    for (int rep = 0; rep < 2; rep++) {
        int gid = t + rep * 512;
        int y = gid >> 4, x0 = (gid & 15) * 4;
        float pin[3][3][6];
#pragma unroll
        for (int r = 0; r < 3; r++)
#pragma unroll
            for (int cc = 0; cc < 6; cc++) {
                pin[0][r][cc] = sm[SM_RF + (y + r) * 66 + x0 + cc];
                pin[1][r][cc] = sm[SM_RF + 4356 + (y + r) * 66 + x0 + cc];
                pin[2][r][cc] = vfc[(y + r) * 66 + x0 + cc];
            }
        bool gy = (y == s1) && (s2 >= x0) && (s2 < x0 + 4);
#pragma unroll 2
        for (int c = 0; c < 10; c++) {
            const float* w = &sm[SM_WQF2 + 2 * ((15 * 10 + c) * 27)];
            float a0 = 0.f, a1 = 0.f, a2 = 0.f, a3 = 0.f;
#pragma unroll
            for (int cin = 0; cin < 3; cin++)
#pragma unroll
                for (int r = 0; r < 3; r++)
#pragma unroll
                    for (int s = 0; s < 3; s++) {
                        float wv = w[2 * (cin * 9 + r * 3 + s)];
                        a0 = fmaf(wv, pin[cin][r][s + 0], a0);
                        a1 = fmaf(wv, pin[cin][r][s + 1], a1);
                        a2 = fmaf(wv, pin[cin][r][s + 2], a2);
                        a3 = fmaf(wv, pin[cin][r][s + 3], a3);
                    }
            psum[c] += (a0 + a1) + (a2 + a3);
            psq[c] += (a0 * a0 + a1 * a1) + (a2 * a2 + a3 * a3);
            if (gy) {
                int d = s2 - x0;
                float qv = (d == 0) ? a0 : (d == 1) ? a1 : (d == 2) ? a2 : a3;
                g_qout[n * 10 + c] = qv;
            }
        }
    }

    // ---- block-reduce BN partials ----------------------------------------
    int lane = t & 31, wid = t >> 5;
#pragma unroll
    for (int c = 0; c < 10; c++) {
        float s = psum[c], q = psq[c];
#pragma unroll
        for (int o = 16; o > 0; o >>= 1) {
            s += __shfl_down_sync(0xffffffffu, s, o);
            q += __shfl_down_sync(0xffffffffu, q, o);
        }
        if (lane == 0) {
            sm[SM_RED + wid * 20 + c] = s;
            sm[SM_RED + wid * 20 + 10 + c] = q;
        }
    }
    __syncthreads();
    if (t < 20) {
        float s = 0.f;
        for (int w = 0; w < 16; w++) s += sm[SM_RED + w * 20 + t];
        g_partial[n * 20 + t] = s;
    }

    // ---- epilogue: last block finalizes BN + dueling heads ---------------
    __shared__ int s_last;
    if (t == 0) {
        __threadfence();                       // release g_partial/g_qout
        unsigned int old = atomicAdd(&g_tick, 1u);
        s_last = (old == N_IMG - 1);
    }
    __syncthreads();
    if (!s_last) return;
    if (t == 0) g_tick = 0;                    // reset for next graph replay
    __threadfence();                           // acquire others' writes

    __shared__ float sMean[10], sScale[10], sBeta[10];
    if (t < 10) {
        double s = 0.0, sq = 0.0;
        for (int nn = 0; nn < N_IMG; nn++) {
            s += (double)g_partial[nn * 20 + t];
            sq += (double)g_partial[nn * 20 + 10 + t];
        }
        double cnt = (double)N_IMG * 4096.0;
        double mu = s / cnt;
        double var = sq / cnt - mu * mu;
        sMean[t] = (float)mu;
        sScale[t] = (float)((double)gamma[t] / sqrt(var + 1e-5));
        sBeta[t] = beta[t];
    }
    __syncthreads();
    if (t < N_IMG) {
        float qn[10];
#pragma unroll
        for (int c = 0; c < 10; c++)
            qn[c] = (g_qout[t * 10 + c] - sMean[c]) * sScale[c] + sBeta[c];
        float a = 0.f;
#pragma unroll
        for (int c = 0; c < 10; c++) a += qn[c] * dw1[c];
        a = fmaxf(a, 0.f);
        float b[8], bm = 0.f;
#pragma unroll
        for (int j = 0; j < 8; j++) {
            float bb = 0.f;
#pragma unroll
            for (int c = 0; c < 10; c++) bb += qn[c] * dw2[j * 10 + c];
            bb = fmaxf(bb, 0.f);
            b[j] = bb;
            bm += bb;
        }
        bm *= 0.125f;
#pragma unroll
        for (int j = 0; j < 8; j++) out[t * 8 + j] = a + b[j] - bm;
    }
}

// ============================================================================
extern "C" void kernel_launch(void* const* d_in, const int* in_sizes, int n_in,
                              void* d_out, int out_size) {
    const float* X    = (const float*)d_in[0];
    const int*   S1   = (const int*)d_in[1];
    const int*   S2   = (const int*)d_in[2];
    const float* whf  = (const float*)d_in[3];   // conv_h_w (150,2,3,3)
    const float* wrf  = (const float*)d_in[4];   // conv_r_w (1,150,3,3)
    const float* wqf  = (const float*)d_in[5];   // conv_q_ws (16,10,3,3,3)
    const float* gam  = (const float*)d_in[6];
    const float* bet  = (const float*)d_in[7];
    const float* w1   = (const float*)d_in[8];
    const float* w2   = (const float*)d_in[9];
    const float* whc  = (const float*)d_in[10];  // vi_conv_h_w
    const float* wrc  = (const float*)d_in[11];  // vi_conv_r_w
    const float* wqc  = (const float*)d_in[12];  // vi_conv_q_ws (16,10,2,3,3)

    cudaFuncSetAttribute(k_main, cudaFuncAttributeMaxDynamicSharedMemorySize, SMEM_BYTES);
    k_main<<<N_IMG, 512, SMEM_BYTES>>>(X, S1, S2, wqf, wqc,
                                       whf, wrf, whc, wrc,
                                       gam, bet, w1, w2, (float*)d_out);
}

// round 5
// speedup vs baseline: 1.1263x; 1.1263x over previous
#include <cuda_runtime.h>
#include <cuda_bf16.h>

#define N_IMG 128
#define KVI   16
typedef unsigned long long ull;

__device__ float g_partial[N_IMG * 20];
__device__ float g_qout[N_IMG * 10];
__device__ unsigned int g_tick;

__device__ __forceinline__ ull pk2(float lo, float hi) {
    ull r; asm("mov.b64 %0,{%1,%2};" : "=l"(r) : "f"(lo), "f"(hi)); return r;
}
__device__ __forceinline__ void upk2(ull v, float& lo, float& hi) {
    asm("mov.b64 {%0,%1},%2;" : "=f"(lo), "=f"(hi) : "l"(v));
}
__device__ __forceinline__ void fma2(ull& d, ull a, ull b) {
    asm("fma.rn.f32x2 %0,%1,%2,%3;" : "=l"(d) : "l"(a), "l"(b), "l"(d));
}

// ---- shared memory layout (float offsets) ----------------------------------
#define SM_WQF2 0        // 8640: fine q weights as (w,w) pairs, (k,c,cin,ky,kx)
#define SM_WQC4 8640     // 3840: coarse q weights float4 {w0,w1,w2,pad}
#define SM_WCF  12480    // 162
#define SM_WCC  12642    // 162
#define SM_W5F  12804    // 50
#define SM_W5C  12854    // 50
#define SM_RED  12904    // 320
#define SM_SC   13224    // 1024 coarse sums 32x32
#define SM_ME   14248    // 4488: m E-pairs  33rp x 68 x 2
#define SM_MO   18736    // 4352: m O-pairs  32rp x 68 x 2
#define SM_RE   23088    // 4488: r E-pairs
#define SM_RO   27576    // 4352: r O-pairs
// phase region (A: X/X1/R1/CVA/CVB, B: v pair buffers)
#define SM_X    31928    // 9248: X pad-2 (also raw wh/wr staging first)
#define SM_X1   41176    // 2592
#define SM_R1   43768    // 1156
#define SM_CVA  44924    // 1156
#define SM_CVB  46080    // 1156
#define SM_VAE  31928    // 4488
#define SM_VAO  36416    // 4352
#define SM_VBE  40768    // 4488
#define SM_VBO  45256    // 4352 -> ends 49608
#define SM_TOT  49608
#define SMEM_BYTES (SM_TOT * 4)
#define NEGINF __int_as_float(0xff800000)

// write value at padded (p,x) into both parity arrays of a fine field
__device__ __forceinline__ void wpair(float* sm, int eb, int ob, int p, int x, float v) {
    sm[eb + (p >> 1) * 136 + 2 * x + (p & 1)] = v;
    sm[ob + ((p - 1) >> 1) * 136 + 2 * x + (1 - (p & 1))] = v;
}

// fused r = conv_r(conv_h(.)) front-end (interior 5x5 / border WC, bit-exact)
template <int H, int ROW, int CHS>
__device__ __forceinline__ float rfront(const float* sxb, const float* w5,
                                        const float* wc, int y, int x) {
    float acc = 0.f;
    if (y >= 1 && y <= H - 2 && x >= 1 && x <= H - 2) {
#pragma unroll
        for (int ci = 0; ci < 2; ci++) {
            const float* xb = &sxb[ci * CHS + y * ROW + x];
#pragma unroll
            for (int fy = 0; fy < 5; fy++)
#pragma unroll
                for (int fx = 0; fx < 5; fx++)
                    acc = fmaf(w5[ci * 25 + fy * 5 + fx], xb[fy * ROW + fx], acc);
        }
    } else {
#pragma unroll
        for (int jy = 0; jy < 3; jy++)
#pragma unroll
            for (int jx = 0; jx < 3; jx++) {
                int py = y + jy - 1, px = x + jx - 1;
                if (py >= 0 && py < H && px >= 0 && px < H) {
                    const float* wcj = &wc[(jy * 3 + jx) * 18];
#pragma unroll
                    for (int ci = 0; ci < 2; ci++) {
                        const float* xb = &sxb[ci * CHS + (py + 1) * ROW + (px + 1)];
#pragma unroll
                        for (int iy = 0; iy < 3; iy++)
#pragma unroll
                            for (int ix = 0; ix < 3; ix++)
                                acc = fmaf(wcj[ci * 9 + iy * 3 + ix], xb[iy * ROW + ix], acc);
                    }
                }
            }
    }
    return acc;
}

#define TAP(base, wo) { \
    const ull* q_ = smu + (base); \
    ull q0=q_[0],q1=q_[1],q2=q_[2],q3=q_[3],q4=q_[4],q5=q_[5]; \
    ull w0=wp[wo],w1=wp[(wo)+1],w2=wp[(wo)+2]; \
    fma2(A0,w0,q0);fma2(A1,w0,q1);fma2(A2,w0,q2);fma2(A3,w0,q3); \
    fma2(A0,w1,q1);fma2(A1,w1,q2);fma2(A2,w1,q3);fma2(A3,w1,q4); \
    fma2(A0,w2,q2);fma2(A1,w2,q3);fma2(A2,w2,q4);fma2(A3,w2,q5); }

__global__ __launch_bounds__(512) void k_main(
    const float* __restrict__ X, const int* __restrict__ S1, const int* __restrict__ S2,
    const float* __restrict__ wqf, const float* __restrict__ wqc,
    const float* __restrict__ whf, const float* __restrict__ wrf,
    const float* __restrict__ whc, const float* __restrict__ wrc,
    const float* __restrict__ gamma, const float* __restrict__ beta,
    const float* __restrict__ dw1, const float* __restrict__ dw2,
    float* __restrict__ out) {
    extern __shared__ float sm[];
    ull* smu = (ull*)sm;
    const int t = threadIdx.x, n = blockIdx.x;

    // ---- stage weights ---------------------------------------------------
    for (int i = t; i < 4320; i += 512) {
        float w = wqf[i];
        sm[SM_WQF2 + 2 * i] = w; sm[SM_WQF2 + 2 * i + 1] = w;
    }
    for (int i = t; i < 960; i += 512) {
        int kc = i / 6, rm = i % 6;
        const float* s = wqc + kc * 18 + (rm / 3) * 9 + (rm % 3) * 3;
        float4 v; v.x = s[0]; v.y = s[1]; v.z = s[2]; v.w = 0.f;
        ((float4*)&sm[SM_WQC4])[i] = v;
    }
    for (int i = t; i < 2700; i += 512) sm[SM_X + i] = whf[i];
    for (int i = t; i < 1350; i += 512) sm[SM_X + 2700 + i] = wrf[i];
    for (int i = t; i < 2700; i += 512) sm[SM_X + 4050 + i] = whc[i];
    for (int i = t; i < 1350; i += 512) sm[SM_X + 6750 + i] = wrc[i];
    __syncthreads();

    // ---- compose WC ------------------------------------------------------
    if (t < 324) {
        int lvl = t / 162, rem = t % 162;
        int j = rem / 18, ci = (rem % 18) / 9, i = rem % 9;
        const float* wr = &sm[SM_X + (lvl ? 6750 : 2700)];
        const float* wh = &sm[SM_X + (lvl ? 4050 : 0)];
        float acc = 0.f;
        for (int o = 0; o < 150; o++)
            acc = fmaf(wr[o * 9 + j], wh[(o * 2 + ci) * 9 + i], acc);
        sm[(lvl ? SM_WCC : SM_WCF) + rem] = acc;
    }
    __syncthreads();

    // ---- W5 + zero pair/phase regions ------------------------------------
    if (t < 100) {
        int lvl = t / 50, rem = t % 50;
        int ci = rem / 25, f = rem % 25, fy = f / 5, fx = f % 5;
        const float* wc = &sm[lvl ? SM_WCC : SM_WCF];
        float acc = 0.f;
        for (int jy = 0; jy < 3; jy++)
            for (int jx = 0; jx < 3; jx++) {
                int iy = fy - jy, ix = fx - jx;
                if (iy >= 0 && iy <= 2 && ix >= 0 && ix <= 2)
                    acc += wc[(jy * 3 + jx) * 18 + ci * 9 + iy * 3 + ix];
            }
        sm[(lvl ? SM_W5C : SM_W5F) + rem] = acc;
    }
    for (int i = SM_ME + t; i < SM_TOT; i += 512) sm[i] = 0.f;
    __syncthreads();

    // ---- X into pad-2 smem ----------------------------------------------
    for (int i = t; i < 8192; i += 512) {
        int ci = i >> 12, y = (i >> 6) & 63, x = i & 63;
        sm[SM_X + ci * 4624 + (y + 2) * 68 + (x + 2)] = X[n * 8192 + i];
    }
    __syncthreads();

    // ---- maxpool ----------------------------------------------------------
    for (int i = t; i < 2048; i += 512) {
        int ci = i >> 10, y = (i >> 5) & 31, x = i & 31;
        const float* b = &sm[SM_X + ci * 4624 + (2 * y + 2) * 68 + (2 * x + 2)];
        sm[SM_X1 + ci * 1296 + (y + 2) * 36 + (x + 2)] =
            fmaxf(fmaxf(b[0], b[1]), fmaxf(b[68], b[69]));
    }
    __syncthreads();

    // ---- coarse r1 --------------------------------------------------------
    for (int i = t; i < 1024; i += 512) {
        int y = i >> 5, x = i & 31;
        sm[SM_R1 + (y + 1) * 34 + (x + 1)] =
            rfront<32, 36, 1296>(&sm[SM_X1], &sm[SM_W5C], &sm[SM_WCC], y, x);
    }
    __syncthreads();

    // ---- coarse VI (scalar, 2 px/thread, register sums) -------------------
    {
        const int cy = t >> 4, cx0 = (t & 15) * 2;
        float scs0 = 0.f, scs1 = 0.f;
        int vc = SM_CVA, vn = SM_CVB;
#pragma unroll 1
        for (int k = 0; k < KVI; k++) {
            float pin[2][3][4];
#pragma unroll
            for (int rr = 0; rr < 3; rr++) {
                float2 a = *(float2*)&sm[SM_R1 + (cy + rr) * 34 + cx0];
                float2 b = *(float2*)&sm[SM_R1 + (cy + rr) * 34 + cx0 + 2];
                pin[0][rr][0] = a.x; pin[0][rr][1] = a.y; pin[0][rr][2] = b.x; pin[0][rr][3] = b.y;
                float2 c2 = *(float2*)&sm[vc + (cy + rr) * 34 + cx0];
                float2 d2 = *(float2*)&sm[vc + (cy + rr) * 34 + cx0 + 2];
                pin[1][rr][0] = c2.x; pin[1][rr][1] = c2.y; pin[1][rr][2] = d2.x; pin[1][rr][3] = d2.y;
            }
            float m0 = NEGINF, m1 = NEGINF;
            const float4* w4 = (const float4*)&sm[SM_WQC4];
#pragma unroll 2
            for (int c = 0; c < 10; c++) {
                float a0 = 0.f, a1 = 0.f;
#pragma unroll
                for (int cin = 0; cin < 2; cin++)
#pragma unroll
                    for (int ky = 0; ky < 3; ky++) {
                        float4 w = w4[(k * 10 + c) * 6 + cin * 3 + ky];
                        const float* q = pin[cin][ky];
                        a0 = fmaf(w.x, q[0], a0); a0 = fmaf(w.y, q[1], a0); a0 = fmaf(w.z, q[2], a0);
                        a1 = fmaf(w.x, q[1], a1); a1 = fmaf(w.y, q[2], a1); a1 = fmaf(w.z, q[3], a1);
                    }
                m0 = fmaxf(m0, a0); m1 = fmaxf(m1, a1);
            }
            sm[vn + (cy + 1) * 34 + cx0 + 1] = m0;
            sm[vn + (cy + 1) * 34 + cx0 + 2] = m1;
            scs0 += m0; scs1 += m1;
            __syncthreads();
            int tp = vc; vc = vn; vn = tp;
        }
        sm[SM_SC + cy * 32 + cx0] = scs0;
        sm[SM_SC + cy * 32 + cx0 + 1] = scs1;
    }
    __syncthreads();

    // ---- upsample (sum/4; jax half-pixel linear == clamp) -> m pairs ------
    for (int i = t; i < 4096; i += 512) {
        int oy = i >> 6, ox = i & 63, ty = oy >> 1, tx = ox >> 1;
        int ya, yb, xa, xb; float wya, wyb, wxa, wxb;
        if ((oy & 1) == 0) { ya = ty > 0 ? ty - 1 : 0; yb = ty; wya = 0.25f; wyb = 0.75f; }
        else { ya = ty; yb = ty < 31 ? ty + 1 : 31; wya = 0.75f; wyb = 0.25f; }
        if ((ox & 1) == 0) { xa = tx > 0 ? tx - 1 : 0; xb = tx; wxa = 0.25f; wxb = 0.75f; }
        else { xa = tx; xb = tx < 31 ? tx + 1 : 31; wxa = 0.75f; wxb = 0.25f; }
        float v = wya * (wxa * sm[SM_SC + ya * 32 + xa] + wxb * sm[SM_SC + ya * 32 + xb]) +
                  wyb * (wxa * sm[SM_SC + yb * 32 + xa] + wxb * sm[SM_SC + yb * 32 + xb]);
        wpair(sm, SM_ME, SM_MO, oy + 1, ox + 1, v * 0.25f);
    }
    // ---- fine r front -> r pairs -----------------------------------------
    for (int i = t; i < 4096; i += 512) {
        int y = i >> 6, x = i & 63;
        wpair(sm, SM_RE, SM_RO, y + 1, x + 1,
              rfront<64, 68, 4624>(&sm[SM_X], &sm[SM_W5F], &sm[SM_WCF], y, x));
    }
    __syncthreads();
    // ---- phase B: zero v pair buffers (kills X/X1/R1/CV*) -----------------
    for (int i = SM_X + t; i < SM_TOT; i += 512) sm[i] = 0.f;
    __syncthreads();

    // ---- fine VI: vertical-pair FFMA2 ------------------------------------
    const int Y = t >> 4, x0 = (t & 15) * 4;
    const int mb0 = SM_ME / 2 + Y * 68 + x0, mb1 = SM_MO / 2 + Y * 68 + x0, mb2 = mb0 + 68;
    const int rb0 = SM_RE / 2 + Y * 68 + x0, rb1 = SM_RO / 2 + Y * 68 + x0, rb2 = rb0 + 68;
    int vE = SM_VAE, vO = SM_VAO, nE = SM_VBE, nO = SM_VBO;
    float S[8];
#pragma unroll
    for (int j = 0; j < 8; j++) S[j] = 0.f;
#pragma unroll 1
    for (int k = 0; k < KVI; k++) {
        const int vb0 = vE / 2 + Y * 68 + x0, vb1 = vO / 2 + Y * 68 + x0, vb2 = vb0 + 68;
        float M[8];
#pragma unroll
        for (int j = 0; j < 8; j++) M[j] = NEGINF;
#pragma unroll 2
        for (int c = 0; c < 10; c++) {
            const ull* wp = smu + (k * 10 + c) * 27;
            ull A0 = 0ull, A1 = 0ull, A2 = 0ull, A3 = 0ull;
            TAP(mb0, 0)  TAP(mb1, 3)  TAP(mb2, 6)
            TAP(rb0, 9)  TAP(rb1, 12) TAP(rb2, 15)
            TAP(vb0, 18) TAP(vb1, 21) TAP(vb2, 24)
            float lo, hi;
            upk2(A0, lo, hi); M[0] = fmaxf(M[0], lo); M[4] = fmaxf(M[4], hi);
            upk2(A1, lo, hi); M[1] = fmaxf(M[1], lo); M[5] = fmaxf(M[5], hi);
            upk2(A2, lo, hi); M[2] = fmaxf(M[2], lo); M[6] = fmaxf(M[6], hi);
            upk2(A3, lo, hi); M[3] = fmaxf(M[3], lo); M[7] = fmaxf(M[7], hi);
        }
        const int ob = nO / 2 + Y * 68 + x0 + 1;
#pragma unroll
        for (int dc = 0; dc < 4; dc++) {
            smu[ob + dc] = pk2(M[dc], M[4 + dc]);
            sm[nE + Y * 136 + 2 * (x0 + 1 + dc) + 1] = M[dc];
            sm[nE + (Y + 1) * 136 + 2 * (x0 + 1 + dc)] = M[4 + dc];
            S[dc] += M[dc]; S[4 + dc] += M[4 + dc];
        }
        __syncthreads();
        int tp = vE; vE = nE; nE = tp; tp = vO; vO = nO; nO = tp;
    }

    // ---- vbar into current v buffer --------------------------------------
#pragma unroll
    for (int dr = 0; dr < 2; dr++)
#pragma unroll
        for (int dc = 0; dc < 4; dc++)
            wpair(sm, vE, vO, 2 * Y + 1 + dr, x0 + 1 + dc, S[dr * 4 + dc] * (1.f / 16.f));
    __syncthreads();

    // ---- final q conv + BN partials + gather -----------------------------
    float pin[3][4][6];
#pragma unroll
    for (int rr = 0; rr < 4; rr++) {
        int p = 2 * Y + rr;
#pragma unroll
        for (int cc = 0; cc < 6; cc++) {
            int x = x0 + cc, off = (p >> 1) * 136 + 2 * x + (p & 1);
            pin[0][rr][cc] = sm[SM_ME + off];
            pin[1][rr][cc] = sm[SM_RE + off];
            pin[2][rr][cc] = sm[vE + off];
        }
    }
    const int s1 = S1[n], s2 = S2[n];
    float psum[10], psq[10];
#pragma unroll 2
    for (int c = 0; c < 10; c++) {
        const int wb = 2 * ((15 * 10 + c) * 27);
        float a[2][4];
#pragma unroll
        for (int j = 0; j < 8; j++) a[j >> 2][j & 3] = 0.f;
#pragma unroll
        for (int cin = 0; cin < 3; cin++)
#pragma unroll
            for (int ky = 0; ky < 3; ky++)
#pragma unroll
                for (int kx = 0; kx < 3; kx++) {
                    float wv = sm[wb + 2 * (cin * 9 + ky * 3 + kx)];
#pragma unroll
                    for (int dr = 0; dr < 2; dr++)
#pragma unroll
                        for (int dc = 0; dc < 4; dc++)
                            a[dr][dc] = fmaf(wv, pin[cin][dr + ky][dc + kx], a[dr][dc]);
                }
        float s = 0.f, q = 0.f;
#pragma unroll
        for (int dr = 0; dr < 2; dr++)
#pragma unroll
            for (int dc = 0; dc < 4; dc++) {
                s += a[dr][dc]; q += a[dr][dc] * a[dr][dc];
                if (2 * Y + dr == s1 && x0 + dc == s2) g_qout[n * 10 + c] = a[dr][dc];
            }
        psum[c] = s; psq[c] = q;
    }

    // ---- block-reduce BN partials ----------------------------------------
    int lane = t & 31, wid = t >> 5;
#pragma unroll
    for (int c = 0; c < 10; c++) {
        float s = psum[c], q = psq[c];
#pragma unroll
        for (int o = 16; o > 0; o >>= 1) {
            s += __shfl_down_sync(0xffffffffu, s, o);
            q += __shfl_down_sync(0xffffffffu, q, o);
        }
        if (lane == 0) { sm[SM_RED + wid * 20 + c] = s; sm[SM_RED + wid * 20 + 10 + c] = q; }
    }
    __syncthreads();
    if (t < 20) {
        float s = 0.f;
        for (int w = 0; w < 16; w++) s += sm[SM_RED + w * 20 + t];
        g_partial[n * 20 + t] = s;
    }

    // ---- epilogue by last block ------------------------------------------
    __shared__ int s_last;
    if (t == 0) {
        __threadfence();
        s_last = (atomicAdd(&g_tick, 1u) == N_IMG - 1);
    }
    __syncthreads();
    if (!s_last) return;
    if (t == 0) g_tick = 0;
    __threadfence();

    __shared__ float sMean[10], sScale[10], sBeta[10];
    if (t < 10) {
        double s = 0.0, sq = 0.0;
        for (int nn = 0; nn < N_IMG; nn++) {
            s += (double)g_partial[nn * 20 + t];
            sq += (double)g_partial[nn * 20 + 10 + t];
        }
        double cnt = (double)N_IMG * 4096.0, mu = s / cnt, var = sq / cnt - mu * mu;
        sMean[t] = (float)mu;
        sScale[t] = (float)((double)gamma[t] / sqrt(var + 1e-5));
        sBeta[t] = beta[t];
    }
    __syncthreads();
    if (t < N_IMG) {
        float qn[10];
#pragma unroll
        for (int c = 0; c < 10; c++)
            qn[c] = (g_qout[t * 10 + c] - sMean[c]) * sScale[c] + sBeta[c];
        float av = 0.f;
#pragma unroll
        for (int c = 0; c < 10; c++) av += qn[c] * dw1[c];
        av = fmaxf(av, 0.f);
        float b[8], bm = 0.f;
#pragma unroll
        for (int j = 0; j < 8; j++) {
            float bb = 0.f;
#pragma unroll
            for (int c = 0; c < 10; c++) bb += qn[c] * dw2[j * 10 + c];
            bb = fmaxf(bb, 0.f);
            b[j] = bb; bm += bb;
        }
        bm *= 0.125f;
#pragma unroll
        for (int j = 0; j < 8; j++) out[t * 8 + j] = av + b[j] - bm;
    }
}

extern "C" void kernel_launch(void* const* d_in, const int* in_sizes, int n_in,
                              void* d_out, int out_size) {
    const float* X   = (const float*)d_in[0];
    const int*   S1  = (const int*)d_in[1];
    const int*   S2  = (const int*)d_in[2];
    const float* whf = (const float*)d_in[3];
    const float* wrf = (const float*)d_in[4];
    const float* wqf = (const float*)d_in[5];
    const float* gam = (const float*)d_in[6];
    const float* bet = (const float*)d_in[7];
    const float* w1  = (const float*)d_in[8];
    const float* w2  = (const float*)d_in[9];
    const float* whc = (const float*)d_in[10];
    const float* wrc = (const float*)d_in[11];
    const float* wqc = (const float*)d_in[12];

    cudaFuncSetAttribute(k_main, cudaFuncAttributeMaxDynamicSharedMemorySize, SMEM_BYTES);
    k_main<<<N_IMG, 512, SMEM_BYTES>>>(X, S1, S2, wqf, wqc, whf, wrf, whc, wrc,
                                       gam, bet, w1, w2, (float*)d_out);
}